// round 11
// baseline (speedup 1.0000x reference)
#include <cuda_runtime.h>
#include <cstdint>

#define NN   50000
#define NE   800000
#define FDIM 128

// ---- scratch (device globals; no allocation allowed) ----
__device__ int   g_deg[NN];
__device__ int   g_fill[NN];
__device__ int   g_rowptr[NN + 1];
__device__ int   g_col[NE];
__device__ float g_invdeg[NN];
__device__ float g_agg[NN * FDIM];
__device__ float g_h[NN * FDIM];
__device__ float g_x[NN * FDIM];          // tf32-rounded copy of x
__device__ float g_Wt[FDIM * 2 * FDIM];   // [n][k], k = 0..255 (Wl | Wr), tf32-rounded

// ===========================================================================
// helpers
// ===========================================================================
__device__ __forceinline__ uint32_t f2tf32(float f) {
    uint32_t u;
    asm("cvt.rna.tf32.f32 %0, %1;" : "=r"(u) : "f"(f));
    return u;
}
__device__ __forceinline__ float rnd(float f) { return __uint_as_float(f2tf32(f)); }

__device__ __forceinline__ uint32_t smem_u32(const void* p) {
    uint32_t a;
    asm("{ .reg .u64 t; cvta.to.shared.u64 t, %1; cvt.u32.u64 %0, t; }"
        : "=r"(a) : "l"(p));
    return a;
}

#define CP16(dst, src) \
    asm volatile("cp.async.cg.shared.global [%0], [%1], 16;" \
                 :: "r"(dst), "l"(src) : "memory")
#define CP_COMMIT  asm volatile("cp.async.commit_group;" ::: "memory")
#define CP_WAIT1   asm volatile("cp.async.wait_group 1;" ::: "memory")
#define CP_WAIT0   asm volatile("cp.async.wait_group 0;" ::: "memory")

__device__ __forceinline__ void mma_tf32(float* d, const uint32_t* a, const uint32_t* b) {
    asm volatile(
        "mma.sync.aligned.m16n8k8.row.col.f32.tf32.tf32.f32 "
        "{%0,%1,%2,%3}, {%4,%5,%6,%7}, {%8,%9}, {%0,%1,%2,%3};"
        : "+f"(d[0]), "+f"(d[1]), "+f"(d[2]), "+f"(d[3])
        : "r"(a[0]), "r"(a[1]), "r"(a[2]), "r"(a[3]), "r"(b[0]), "r"(b[1]));
}

// ===========================================================================
// CSR build
// ===========================================================================
__global__ void k_zero() {
    int i = blockIdx.x * blockDim.x + threadIdx.x;
    if (i < NN) { g_deg[i] = 0; g_fill[i] = 0; }
}

__global__ void k_hist(const int* __restrict__ dst) {
    int t = blockIdx.x * blockDim.x + threadIdx.x;
    int e0 = t * 4;
    if (e0 + 3 < NE) {
        int d0 = dst[e0], d1 = dst[e0 + 1], d2 = dst[e0 + 2], d3 = dst[e0 + 3];
        atomicAdd(&g_deg[d0], 1);
        atomicAdd(&g_deg[d1], 1);
        atomicAdd(&g_deg[d2], 1);
        atomicAdd(&g_deg[d3], 1);
    } else {
        for (int e = e0; e < NE; e++) atomicAdd(&g_deg[dst[e]], 1);
    }
}

__global__ void k_scan() {
    const int T = 1024;
    const int CH = (NN + T - 1) / T;
    __shared__ int ssum[T];
    int t = threadIdx.x;
    int base = t * CH;
    int s = 0;
    for (int j = 0; j < CH; j++) {
        int idx = base + j;
        if (idx < NN) s += g_deg[idx];
    }
    ssum[t] = s;
    __syncthreads();
    for (int off = 1; off < T; off <<= 1) {
        int v = 0;
        if (t >= off) v = ssum[t - off];
        __syncthreads();
        if (t >= off) ssum[t] += v;
        __syncthreads();
    }
    int run = (t > 0) ? ssum[t - 1] : 0;
    for (int j = 0; j < CH; j++) {
        int idx = base + j;
        if (idx < NN) {
            g_rowptr[idx] = run;
            int d = g_deg[idx];
            g_invdeg[idx] = (d > 0) ? (1.0f / (float)d) : 0.0f;
            run += d;
        }
    }
    if (t == T - 1) g_rowptr[NN] = run;
}

__global__ void k_fill(const int* __restrict__ src, const int* __restrict__ dst) {
    int t = blockIdx.x * blockDim.x + threadIdx.x;
    int e0 = t * 4;
    if (e0 + 3 < NE) {
        int d0 = dst[e0], d1 = dst[e0 + 1], d2 = dst[e0 + 2], d3 = dst[e0 + 3];
        int s0 = src[e0], s1 = src[e0 + 1], s2 = src[e0 + 2], s3 = src[e0 + 3];
        int p0 = g_rowptr[d0] + atomicAdd(&g_fill[d0], 1);
        int p1 = g_rowptr[d1] + atomicAdd(&g_fill[d1], 1);
        int p2 = g_rowptr[d2] + atomicAdd(&g_fill[d2], 1);
        int p3 = g_rowptr[d3] + atomicAdd(&g_fill[d3], 1);
        g_col[p0] = s0;
        g_col[p1] = s1;
        g_col[p2] = s2;
        g_col[p3] = s3;
    } else {
        for (int e = e0; e < NE; e++) {
            int d = dst[e];
            int pos = g_rowptr[d] + atomicAdd(&g_fill[d], 1);
            g_col[pos] = src[e];
        }
    }
}

// ===========================================================================
// one-time tf32 rounding of x, and transposed+rounded weights
// ===========================================================================
__global__ void k_roundx(const float* __restrict__ x) {
    int i = blockIdx.x * blockDim.x + threadIdx.x;
    if (i < NN * FDIM / 4) {
        float4 v = __ldg((const float4*)x + i);
        v.x = rnd(v.x); v.y = rnd(v.y); v.z = rnd(v.z); v.w = rnd(v.w);
        ((float4*)g_x)[i] = v;
    }
}

__global__ void k_transW(const float* __restrict__ W1, const float* __restrict__ W2) {
    int i = blockIdx.x * blockDim.x + threadIdx.x;
    if (i < FDIM * FDIM) {
        int k = i >> 7, n = i & 127;
        g_Wt[n * 256 + k]       = rnd(W1[i]);
        g_Wt[n * 256 + 128 + k] = rnd(W2[i]);
    }
}

// ===========================================================================
// mean-aggregate into g_agg (one warp per node; feat==nullptr -> g_h)
// output is tf32-rounded (feeds tensor-core GEMM directly)
// ===========================================================================
__global__ __launch_bounds__(256) void k_agg(const float* __restrict__ feat) {
    int warp = (blockIdx.x * blockDim.x + threadIdx.x) >> 5;
    int lane = threadIdx.x & 31;
    if (warp >= NN) return;
    const float4* fv = feat ? (const float4*)feat : (const float4*)g_h;
    int beg = g_rowptr[warp], end = g_rowptr[warp + 1];
    float4 a0 = make_float4(0.f, 0.f, 0.f, 0.f);
    float4 a1 = make_float4(0.f, 0.f, 0.f, 0.f);
    float4 a2 = make_float4(0.f, 0.f, 0.f, 0.f);
    float4 a3 = make_float4(0.f, 0.f, 0.f, 0.f);
    int e = beg;
    for (; e + 3 < end; e += 4) {
        int s0 = g_col[e],     s1 = g_col[e + 1];
        int s2 = g_col[e + 2], s3 = g_col[e + 3];
        float4 v0 = __ldg(fv + s0 * 32 + lane);
        float4 v1 = __ldg(fv + s1 * 32 + lane);
        float4 v2 = __ldg(fv + s2 * 32 + lane);
        float4 v3 = __ldg(fv + s3 * 32 + lane);
        a0.x += v0.x; a0.y += v0.y; a0.z += v0.z; a0.w += v0.w;
        a1.x += v1.x; a1.y += v1.y; a1.z += v1.z; a1.w += v1.w;
        a2.x += v2.x; a2.y += v2.y; a2.z += v2.z; a2.w += v2.w;
        a3.x += v3.x; a3.y += v3.y; a3.z += v3.z; a3.w += v3.w;
    }
    for (; e < end; e++) {
        int s0 = g_col[e];
        float4 v0 = __ldg(fv + s0 * 32 + lane);
        a0.x += v0.x; a0.y += v0.y; a0.z += v0.z; a0.w += v0.w;
    }
    float inv = g_invdeg[warp];
    float4 r;
    r.x = rnd(((a0.x + a1.x) + (a2.x + a3.x)) * inv);
    r.y = rnd(((a0.y + a1.y) + (a2.y + a3.y)) * inv);
    r.z = rnd(((a0.z + a1.z) + (a2.z + a3.z)) * inv);
    r.w = rnd(((a0.w + a1.w) + (a2.w + a3.w)) * inv);
    ((float4*)g_agg)[warp * 32 + lane] = r;
}

// ===========================================================================
// tf32 mma.sync fused dual GEMM, cp.async double-buffered:
//   out = g_agg @ Wl^T + A2 @ Wr^T + bias
//   a2_sel: 0 -> g_x, 1 -> g_h ; out_in==nullptr -> g_h
//   mode 1: relu + tf32-round stored output (layer 0); mode 0: plain (layer 1)
// CTA tile 128x128, 8 warps each 64x32, BK=16 chunks (8 from g_agg, 8 from A2)
// ===========================================================================
#define BK 16
#define SR 20   // smem row stride in floats: 8 rows hit distinct bank groups, 16B-aligned

__global__ __launch_bounds__(256) void k_gemm(
    int a2_sel, const float* __restrict__ bias,
    float* __restrict__ out_in, int mode)
{
    __shared__ uint32_t sA[2][128 * SR];
    __shared__ uint32_t sB[2][128 * SR];

    const float* A1 = (const float*)g_agg;
    const float* A2 = a2_sel ? (const float*)g_h : (const float*)g_x;
    float* outp = out_in ? out_in : (float*)g_h;

    int tid  = threadIdx.x;
    int wid  = tid >> 5;
    int lane = tid & 31;
    int row0 = blockIdx.x * 128;

    int wr = (wid & 1) * 64;
    int wc = (wid >> 1) * 32;
    int qr = lane >> 2;
    int qc = lane & 3;

    uint32_t baseA[2], baseB[2];
    baseA[0] = smem_u32(&sA[0][0]); baseA[1] = smem_u32(&sA[1][0]);
    baseB[0] = smem_u32(&sB[0][0]); baseB[1] = smem_u32(&sB[1][0]);

    int r_st = tid >> 2;          // 0..63 : handles rows r_st, r_st+64
    int q_st = tid & 3;           // granule 0..3

    float acc[4][4][4];
#pragma unroll
    for (int mi = 0; mi < 4; mi++)
#pragma unroll
        for (int ni = 0; ni < 4; ni++)
#pragma unroll
            for (int r = 0; r < 4; r++) acc[mi][ni][r] = 0.f;

    // ---- staging (cp.async, 16B granules) ----
    auto stage = [&](int buf, int c) {
        const float* Asrc = (c < 8) ? A1 : A2;
        int cb = (c & 7) * BK;
#pragma unroll
        for (int j = 0; j < 2; j++) {
            int r = r_st + j * 64;
            int gr = row0 + r;
            if (gr >= NN) gr = NN - 1;   // clamp: rows >= NN never stored
            const float* srcA = Asrc + (size_t)gr * FDIM + cb + q_st * 4;
            CP16(baseA[buf] + (uint32_t)(r * SR + q_st * 4) * 4, srcA);
            const float* srcB = g_Wt + r * 256 + c * BK + q_st * 4;
            CP16(baseB[buf] + (uint32_t)(r * SR + q_st * 4) * 4, srcB);
        }
    };

    stage(0, 0);
    CP_COMMIT;

    for (int c = 0; c < 16; c++) {
        if (c < 15) {
            stage((c + 1) & 1, c + 1);
            CP_COMMIT;
            CP_WAIT1;
        } else {
            CP_WAIT0;
        }
        __syncthreads();

        const uint32_t* SA = sA[c & 1];
        const uint32_t* SB = sB[c & 1];
#pragma unroll
        for (int ks = 0; ks < 2; ks++) {
            int k0 = ks * 8;
            uint32_t a[4][4];
#pragma unroll
            for (int mi = 0; mi < 4; mi++) {
                int r0 = wr + mi * 16;
                a[mi][0] = SA[(r0 + qr)     * SR + k0 + qc];
                a[mi][1] = SA[(r0 + qr + 8) * SR + k0 + qc];
                a[mi][2] = SA[(r0 + qr)     * SR + k0 + qc + 4];
                a[mi][3] = SA[(r0 + qr + 8) * SR + k0 + qc + 4];
            }
            uint32_t b[4][2];
#pragma unroll
            for (int ni = 0; ni < 4; ni++) {
                int n0 = wc + ni * 8;
                b[ni][0] = SB[(n0 + qr) * SR + k0 + qc];
                b[ni][1] = SB[(n0 + qr) * SR + k0 + qc + 4];
            }
#pragma unroll
            for (int mi = 0; mi < 4; mi++)
#pragma unroll
                for (int ni = 0; ni < 4; ni++)
                    mma_tf32(acc[mi][ni], a[mi], b[ni]);
        }
        __syncthreads();
    }

    // ---- epilogue ----
#pragma unroll
    for (int mi = 0; mi < 4; mi++) {
        int rA = row0 + wr + mi * 16 + qr;
        int rB = rA + 8;
#pragma unroll
        for (int ni = 0; ni < 4; ni++) {
            int col = wc + ni * 8 + qc * 2;
            float b0 = __ldg(bias + col);
            float b1 = __ldg(bias + col + 1);
            float v0 = acc[mi][ni][0] + b0;
            float v1 = acc[mi][ni][1] + b1;
            float v2 = acc[mi][ni][2] + b0;
            float v3 = acc[mi][ni][3] + b1;
            if (mode) {   // relu + tf32-round (internal h tensor)
                v0 = rnd(fmaxf(v0, 0.f)); v1 = rnd(fmaxf(v1, 0.f));
                v2 = rnd(fmaxf(v2, 0.f)); v3 = rnd(fmaxf(v3, 0.f));
            }
            if (rA < NN) *(float2*)(outp + (size_t)rA * FDIM + col) = make_float2(v0, v1);
            if (rB < NN) *(float2*)(outp + (size_t)rB * FDIM + col) = make_float2(v2, v3);
        }
    }
}

// ===========================================================================
// final layer (C=4): out[i,c] = g_agg[i]@Wl2[:,c] + h2[i]@Wr2[:,c] + b[c]
// ===========================================================================
__global__ __launch_bounds__(256) void k_out(
    const float* __restrict__ h2,
    const float* __restrict__ Wl, const float* __restrict__ Wr,
    const float* __restrict__ b, float* __restrict__ outp)
{
    __shared__ float sWl[FDIM * 4];
    __shared__ float sWr[FDIM * 4];
    __shared__ float sb[4];
    int tid = threadIdx.x;
    for (int i = tid; i < FDIM * 4; i += blockDim.x) {
        sWl[i] = Wl[i];
        sWr[i] = Wr[i];
    }
    if (tid < 4) sb[tid] = b[tid];
    __syncthreads();

    int warp = (blockIdx.x * blockDim.x + tid) >> 5;
    int lane = tid & 31;
    if (warp >= NN) return;

    float4 m = ((const float4*)g_agg)[warp * 32 + lane];
    float4 x = ((const float4*)h2)[warp * 32 + lane];
    float mv[4] = {m.x, m.y, m.z, m.w};
    float xv[4] = {x.x, x.y, x.z, x.w};
    float acc[4] = {0.f, 0.f, 0.f, 0.f};
#pragma unroll
    for (int j = 0; j < 4; j++) {
        int f = 4 * lane + j;
#pragma unroll
        for (int c = 0; c < 4; c++)
            acc[c] += mv[j] * sWl[f * 4 + c] + xv[j] * sWr[f * 4 + c];
    }
#pragma unroll
    for (int off = 16; off > 0; off >>= 1) {
#pragma unroll
        for (int c = 0; c < 4; c++)
            acc[c] += __shfl_xor_sync(0xffffffffu, acc[c], off);
    }
    if (lane == 0) {
#pragma unroll
        for (int c = 0; c < 4; c++) {
            float v = acc[c] + sb[c];
            outp[warp * 4 + c] = v;
            outp[NN * 4 + warp * 4 + c] = v;
        }
    }
}

// ===========================================================================
extern "C" void kernel_launch(void* const* d_in, const int* in_sizes, int n_in,
                              void* d_out, int out_size) {
    const float* x   = (const float*)d_in[0];
    const int*   ei  = (const int*)d_in[1];
    const int*   src = ei;
    const int*   dst = ei + NE;
    const float* Wl0 = (const float*)d_in[2];
    const float* bl0 = (const float*)d_in[3];
    const float* Wr0 = (const float*)d_in[4];
    const float* Wl1 = (const float*)d_in[5];
    const float* bl1 = (const float*)d_in[6];
    const float* Wr1 = (const float*)d_in[7];
    const float* Wl2 = (const float*)d_in[8];
    const float* bl2 = (const float*)d_in[9];
    const float* Wr2 = (const float*)d_in[10];

    float* outp = (float*)d_out;
    float* h2   = outp + 2 * NN * 4;   // h2 lives directly in d_out

    // CSR build (by destination)
    k_zero<<<(NN + 255) / 256, 256>>>();
    k_hist<<<(NE / 4 + 255) / 256, 256>>>(dst);
    k_scan<<<1, 1024>>>();
    k_fill<<<(NE / 4 + 255) / 256, 256>>>(src, dst);

    // one-time tf32 rounding of x
    k_roundx<<<(NN * FDIM / 4 + 255) / 256, 256>>>(x);

    const int aggBlocks  = (NN + 7) / 8;
    const int gemmBlocks = (NN + 127) / 128;   // 391
    const int twBlocks   = (FDIM * FDIM + 255) / 256;

    // layer 0: g_h = relu(mean(x)@Wl0 + x@Wr0 + bl0)   [output tf32-rounded]
    k_transW<<<twBlocks, 256>>>(Wl0, Wr0);
    k_agg<<<aggBlocks, 256>>>(x);
    k_gemm<<<gemmBlocks, 256>>>(0, bl0, nullptr, 1);

    // layer 1: h2 = mean(g_h)@Wl1 + g_h@Wr1 + bl1   (not rounded; compared output)
    k_transW<<<twBlocks, 256>>>(Wl1, Wr1);
    k_agg<<<aggBlocks, 256>>>(nullptr);
    k_gemm<<<gemmBlocks, 256>>>(1, bl1, h2, 0);

    // layer 2: out = mean(h2)@Wl2 + h2@Wr2 + bl2  (C=4), duplicated
    k_agg<<<aggBlocks, 256>>>(h2);
    k_out<<<aggBlocks, 256>>>(h2, Wl2, Wr2, bl2, outp);
}